// round 7
// baseline (speedup 1.0000x reference)
#include <cuda_runtime.h>

// Depthwise 3x3 conv, N=16, C=256, H=W=128, pad=1, stride=1, fp32, + bias.
// One warp = full 128-wide row as 32 float4. R7: 32-row strips (4 warps = one
// full plane per block) -> halo read amplification 12.5% -> 6.25%; plain
// cached reads so duplicated boundary rows can hit L1/L2; streaming stores.

namespace {
constexpr int W4 = 32;        // float4 per row (W=128)
constexpr int H = 128;
constexpr int C = 256;
constexpr int ROWS_PER_WARP = 32;
constexpr int WARPS = 4;                 // 4 * 32 = 128 rows = full plane
constexpr int THREADS = WARPS * 32;      // 128
constexpr int UNROLL = 4;

__device__ __forceinline__ void halos(float4 q, int lane, float& lh, float& rh) {
    lh = __shfl_up_sync(0xFFFFFFFFu, q.w, 1);
    rh = __shfl_down_sync(0xFFFFFFFFu, q.x, 1);
    if (lane == 0)  lh = 0.0f;
    if (lane == 31) rh = 0.0f;
}

__device__ __forceinline__ void row_contrib(float4& acc, float4 q, float lh, float rh,
                                            float wa, float wb, float wc) {
    acc.x = fmaf(wa, lh,  fmaf(wb, q.x, fmaf(wc, q.y, acc.x)));
    acc.y = fmaf(wa, q.x, fmaf(wb, q.y, fmaf(wc, q.z, acc.y)));
    acc.z = fmaf(wa, q.y, fmaf(wb, q.z, fmaf(wc, q.w, acc.z)));
    acc.w = fmaf(wa, q.z, fmaf(wb, q.w, fmaf(wc, rh,  acc.w)));
}
}  // namespace

__global__ __launch_bounds__(THREADS, 10)
void dwconv3x3_kernel(const float* __restrict__ x,
                      const float* __restrict__ weight,
                      const float* __restrict__ bias,
                      float* __restrict__ out) {
    const int plane = blockIdx.x;                  // n*C + c
    const int c = plane & (C - 1);
    const int lane = threadIdx.x & 31;
    const int warp = threadIdx.x >> 5;

    const float* w = weight + c * 9;
    const float w00 = __ldg(w + 0), w01 = __ldg(w + 1), w02 = __ldg(w + 2);
    const float w10 = __ldg(w + 3), w11 = __ldg(w + 4), w12 = __ldg(w + 5);
    const float w20 = __ldg(w + 6), w21 = __ldg(w + 7), w22 = __ldg(w + 8);
    const float b = __ldg(bias + c);

    const int y0 = warp * ROWS_PER_WARP;
    const size_t base = (size_t)plane * (H * W4) + (size_t)y0 * W4 + lane;
    const float4* __restrict__ rd = reinterpret_cast<const float4*>(x) + base;
    float4* __restrict__ wr = reinterpret_cast<float4*>(out) + base;

    const float4 Z = make_float4(0.f, 0.f, 0.f, 0.f);
    const bool last_strip = (warp == WARPS - 1);

    // Rolling window: qm = row r-1, qc = row r.
    float4 qm, qc;
    float lm, rm, lc, rc;

    qm = (y0 > 0) ? __ldg(rd - W4) : Z;
    qc = __ldg(rd);
    halos(qm, lane, lm, rm);
    halos(qc, lane, lc, rc);

    const float4* pr = rd + W4;      // next row to load (row y0+1)

    #pragma unroll
    for (int rb = 0; rb < ROWS_PER_WARP / UNROLL; ++rb) {
        // Batch-issue UNROLL independent loads.
        float4 p[UNROLL];
        if (last_strip && rb == ROWS_PER_WARP / UNROLL - 1) {
            #pragma unroll
            for (int i = 0; i < UNROLL - 1; ++i) p[i] = __ldg(pr + i * W4);
            p[UNROLL - 1] = Z;
        } else {
            #pragma unroll
            for (int i = 0; i < UNROLL; ++i) p[i] = __ldg(pr + i * W4);
        }
        pr += UNROLL * W4;

        // Compute + store the UNROLL output rows.
        #pragma unroll
        for (int i = 0; i < UNROLL; ++i) {
            float lp, rp;
            halos(p[i], lane, lp, rp);

            float4 acc = make_float4(b, b, b, b);
            row_contrib(acc, qm, lm, rm, w00, w01, w02);
            row_contrib(acc, qc, lc, rc, w10, w11, w12);
            row_contrib(acc, p[i], lp, rp, w20, w21, w22);

            __stcs(wr + (rb * UNROLL + i) * W4, acc);

            qm = qc; lm = lc; rm = rc;
            qc = p[i]; lc = lp; rc = rp;
        }
    }
}

extern "C" void kernel_launch(void* const* d_in, const int* in_sizes, int n_in,
                              void* d_out, int out_size) {
    const float* x      = (const float*)d_in[0];
    const float* weight = (const float*)d_in[1];
    const float* bias   = (const float*)d_in[2];
    float* out          = (float*)d_out;

    const int n_blocks = 16 * C;   // 4096 planes, one block each
    dwconv3x3_kernel<<<n_blocks, THREADS>>>(x, weight, bias, out);
}

// round 8
// speedup vs baseline: 1.0437x; 1.0437x over previous
#include <cuda_runtime.h>

// Depthwise 3x3 conv, N=16, C=256, H=W=128, pad=1, stride=1, fp32, + bias.
// One warp = full 128-wide row as 32 float4; 16 rows/warp; 2 blocks/plane
// (best-measured R4 config, memory-roofline-bound at ~6.4 TB/s).
// R8: UNROLL 4 -> 8 (MLP 8, longer contiguous read bursts, less loop overhead).

namespace {
constexpr int W4 = 32;        // float4 per row (W=128)
constexpr int H = 128;
constexpr int C = 256;
constexpr int ROWS_PER_WARP = 16;
constexpr int WARPS = 4;                       // block covers 64 rows
constexpr int THREADS = WARPS * 32;            // 128
constexpr int BLOCKS_PER_PLANE = H / (WARPS * ROWS_PER_WARP);  // 2
constexpr int UNROLL = 8;

__device__ __forceinline__ void halos(float4 q, int lane, float& lh, float& rh) {
    lh = __shfl_up_sync(0xFFFFFFFFu, q.w, 1);
    rh = __shfl_down_sync(0xFFFFFFFFu, q.x, 1);
    if (lane == 0)  lh = 0.0f;
    if (lane == 31) rh = 0.0f;
}

__device__ __forceinline__ void row_contrib(float4& acc, float4 q, float lh, float rh,
                                            float wa, float wb, float wc) {
    acc.x = fmaf(wa, lh,  fmaf(wb, q.x, fmaf(wc, q.y, acc.x)));
    acc.y = fmaf(wa, q.x, fmaf(wb, q.y, fmaf(wc, q.z, acc.y)));
    acc.z = fmaf(wa, q.y, fmaf(wb, q.z, fmaf(wc, q.w, acc.z)));
    acc.w = fmaf(wa, q.z, fmaf(wb, q.w, fmaf(wc, rh,  acc.w)));
}
}  // namespace

__global__ __launch_bounds__(THREADS, 8)
void dwconv3x3_kernel(const float* __restrict__ x,
                      const float* __restrict__ weight,
                      const float* __restrict__ bias,
                      float* __restrict__ out) {
    const int blk   = blockIdx.x;
    const int plane = blk >> 1;                    // n*C + c  (BLOCKS_PER_PLANE = 2)
    const int half  = blk & 1;
    const int c = plane & (C - 1);
    const int lane = threadIdx.x & 31;
    const int warp = threadIdx.x >> 5;

    const float* w = weight + c * 9;
    const float w00 = __ldg(w + 0), w01 = __ldg(w + 1), w02 = __ldg(w + 2);
    const float w10 = __ldg(w + 3), w11 = __ldg(w + 4), w12 = __ldg(w + 5);
    const float w20 = __ldg(w + 6), w21 = __ldg(w + 7), w22 = __ldg(w + 8);
    const float b = __ldg(bias + c);

    const int y0 = (half * WARPS + warp) * ROWS_PER_WARP;
    const size_t base = (size_t)plane * (H * W4) + (size_t)y0 * W4 + lane;
    const float4* __restrict__ rd = reinterpret_cast<const float4*>(x) + base;
    float4* __restrict__ wr = reinterpret_cast<float4*>(out) + base;

    const float4 Z = make_float4(0.f, 0.f, 0.f, 0.f);
    const bool last_strip = (y0 + ROWS_PER_WARP >= H);

    // Rolling window: qm = row r-1, qc = row r.
    float4 qm, qc;
    float lm, rm, lc, rc;

    qm = (y0 > 0) ? __ldcs(rd - W4) : Z;
    qc = __ldcs(rd);
    halos(qm, lane, lm, rm);
    halos(qc, lane, lc, rc);

    const float4* pr = rd + W4;      // next row to load (row y0+1)

    #pragma unroll
    for (int rb = 0; rb < ROWS_PER_WARP / UNROLL; ++rb) {
        // Batch-issue UNROLL independent loads (rows following the window).
        float4 p[UNROLL];
        if (last_strip && rb == ROWS_PER_WARP / UNROLL - 1) {
            // Only the final batch of the bottom strip touches the H boundary.
            #pragma unroll
            for (int i = 0; i < UNROLL - 1; ++i) p[i] = __ldcs(pr + i * W4);
            p[UNROLL - 1] = Z;
        } else {
            #pragma unroll
            for (int i = 0; i < UNROLL; ++i) p[i] = __ldcs(pr + i * W4);
        }
        pr += UNROLL * W4;

        // Compute + store the UNROLL output rows.
        #pragma unroll
        for (int i = 0; i < UNROLL; ++i) {
            float lp, rp;
            halos(p[i], lane, lp, rp);

            float4 acc = make_float4(b, b, b, b);
            row_contrib(acc, qm, lm, rm, w00, w01, w02);
            row_contrib(acc, qc, lc, rc, w10, w11, w12);
            row_contrib(acc, p[i], lp, rp, w20, w21, w22);

            __stcs(wr + (rb * UNROLL + i) * W4, acc);

            qm = qc; lm = lc; rm = rc;
            qc = p[i]; lc = lp; rc = rp;
        }
    }
}

extern "C" void kernel_launch(void* const* d_in, const int* in_sizes, int n_in,
                              void* d_out, int out_size) {
    const float* x      = (const float*)d_in[0];
    const float* weight = (const float*)d_in[1];
    const float* bias   = (const float*)d_in[2];
    float* out          = (float*)d_out;

    const int n_blocks = 16 * C * BLOCKS_PER_PLANE;   // 8192
    dwconv3x3_kernel<<<n_blocks, THREADS>>>(x, weight, bias, out);
}

// round 9
// speedup vs baseline: 1.0523x; 1.0082x over previous
#include <cuda_runtime.h>

// Depthwise 3x3 conv, N=16, C=256, H=W=128, pad=1, stride=1, fp32, + bias.
// One warp = full 128-wide row as 32 float4; 16 rows/warp; 2 blocks/plane.
// R9: whole strip as ONE load batch (16 back-to-back LDG.128 = 8KB contiguous
// read burst per warp, then 8KB store burst) to maximize HBM stream efficiency.

namespace {
constexpr int W4 = 32;        // float4 per row (W=128)
constexpr int H = 128;
constexpr int C = 256;
constexpr int ROWS_PER_WARP = 16;
constexpr int WARPS = 4;                       // block covers 64 rows
constexpr int THREADS = WARPS * 32;            // 128
constexpr int BLOCKS_PER_PLANE = H / (WARPS * ROWS_PER_WARP);  // 2

__device__ __forceinline__ void halos(float4 q, int lane, float& lh, float& rh) {
    lh = __shfl_up_sync(0xFFFFFFFFu, q.w, 1);
    rh = __shfl_down_sync(0xFFFFFFFFu, q.x, 1);
    if (lane == 0)  lh = 0.0f;
    if (lane == 31) rh = 0.0f;
}

__device__ __forceinline__ void row_contrib(float4& acc, float4 q, float lh, float rh,
                                            float wa, float wb, float wc) {
    acc.x = fmaf(wa, lh,  fmaf(wb, q.x, fmaf(wc, q.y, acc.x)));
    acc.y = fmaf(wa, q.x, fmaf(wb, q.y, fmaf(wc, q.z, acc.y)));
    acc.z = fmaf(wa, q.y, fmaf(wb, q.z, fmaf(wc, q.w, acc.z)));
    acc.w = fmaf(wa, q.z, fmaf(wb, q.w, fmaf(wc, rh,  acc.w)));
}
}  // namespace

__global__ __launch_bounds__(THREADS, 4)
void dwconv3x3_kernel(const float* __restrict__ x,
                      const float* __restrict__ weight,
                      const float* __restrict__ bias,
                      float* __restrict__ out) {
    const int blk   = blockIdx.x;
    const int plane = blk >> 1;                    // n*C + c  (BLOCKS_PER_PLANE = 2)
    const int half  = blk & 1;
    const int c = plane & (C - 1);
    const int lane = threadIdx.x & 31;
    const int warp = threadIdx.x >> 5;

    const float* w = weight + c * 9;
    const float w00 = __ldg(w + 0), w01 = __ldg(w + 1), w02 = __ldg(w + 2);
    const float w10 = __ldg(w + 3), w11 = __ldg(w + 4), w12 = __ldg(w + 5);
    const float w20 = __ldg(w + 6), w21 = __ldg(w + 7), w22 = __ldg(w + 8);
    const float b = __ldg(bias + c);

    const int y0 = (half * WARPS + warp) * ROWS_PER_WARP;
    const size_t base = (size_t)plane * (H * W4) + (size_t)y0 * W4 + lane;
    const float4* __restrict__ rd = reinterpret_cast<const float4*>(x) + base;
    float4* __restrict__ wr = reinterpret_cast<float4*>(out) + base;

    const float4 Z = make_float4(0.f, 0.f, 0.f, 0.f);
    const bool last_strip = (y0 + ROWS_PER_WARP >= H);

    // Window head: rows y0-1 and y0.
    float4 qm = (y0 > 0) ? __ldcs(rd - W4) : Z;
    float4 qc = __ldcs(rd);

    // Single contiguous 8KB read burst: rows y0+1 .. y0+16.
    float4 p[ROWS_PER_WARP];
    #pragma unroll
    for (int i = 0; i < ROWS_PER_WARP - 1; ++i) p[i] = __ldcs(rd + (i + 1) * W4);
    p[ROWS_PER_WARP - 1] = last_strip ? Z : __ldcs(rd + ROWS_PER_WARP * W4);

    float lm, rm, lc, rc;
    halos(qm, lane, lm, rm);
    halos(qc, lane, lc, rc);

    // Compute + contiguous store burst.
    #pragma unroll
    for (int i = 0; i < ROWS_PER_WARP; ++i) {
        float lp, rp;
        halos(p[i], lane, lp, rp);

        float4 acc = make_float4(b, b, b, b);
        row_contrib(acc, qm, lm, rm, w00, w01, w02);
        row_contrib(acc, qc, lc, rc, w10, w11, w12);
        row_contrib(acc, p[i], lp, rp, w20, w21, w22);

        __stcs(wr + i * W4, acc);

        qm = qc; lm = lc; rm = rc;
        qc = p[i]; lc = lp; rc = rp;
    }
}

extern "C" void kernel_launch(void* const* d_in, const int* in_sizes, int n_in,
                              void* d_out, int out_size) {
    const float* x      = (const float*)d_in[0];
    const float* weight = (const float*)d_in[1];
    const float* bias   = (const float*)d_in[2];
    float* out          = (float*)d_out;

    const int n_blocks = 16 * C * BLOCKS_PER_PLANE;   // 8192
    dwconv3x3_kernel<<<n_blocks, THREADS>>>(x, weight, bias, out);
}

// round 12
// speedup vs baseline: 1.0548x; 1.0023x over previous
#include <cuda_runtime.h>

// Depthwise 3x3 conv, N=16, C=256, H=W=128, pad=1, stride=1, fp32, + bias.
// One warp = full 128-wide row as 32 float4; 16 rows/warp; 2 blocks/plane.
// R10: explicit 2-stage pipeline of two 8-row load bursts: batch1's 4KB
// contiguous read burst is issued BEFORE batch0's compute, so the read stream
// never stalls while keeping R8's deep-burst DRAM efficiency.

namespace {
constexpr int W4 = 32;        // float4 per row (W=128)
constexpr int H = 128;
constexpr int C = 256;
constexpr int ROWS_PER_WARP = 16;
constexpr int WARPS = 4;                       // block covers 64 rows
constexpr int THREADS = WARPS * 32;            // 128
constexpr int BLOCKS_PER_PLANE = H / (WARPS * ROWS_PER_WARP);  // 2
constexpr int B = 8;                           // rows per batch

__device__ __forceinline__ void halos(float4 q, int lane, float& lh, float& rh) {
    lh = __shfl_up_sync(0xFFFFFFFFu, q.w, 1);
    rh = __shfl_down_sync(0xFFFFFFFFu, q.x, 1);
    if (lane == 0)  lh = 0.0f;
    if (lane == 31) rh = 0.0f;
}

__device__ __forceinline__ void row_contrib(float4& acc, float4 q, float lh, float rh,
                                            float wa, float wb, float wc) {
    acc.x = fmaf(wa, lh,  fmaf(wb, q.x, fmaf(wc, q.y, acc.x)));
    acc.y = fmaf(wa, q.x, fmaf(wb, q.y, fmaf(wc, q.z, acc.y)));
    acc.z = fmaf(wa, q.y, fmaf(wb, q.z, fmaf(wc, q.w, acc.z)));
    acc.w = fmaf(wa, q.z, fmaf(wb, q.w, fmaf(wc, rh,  acc.w)));
}
}  // namespace

__global__ __launch_bounds__(THREADS, 5)
void dwconv3x3_kernel(const float* __restrict__ x,
                      const float* __restrict__ weight,
                      const float* __restrict__ bias,
                      float* __restrict__ out) {
    const int blk   = blockIdx.x;
    const int plane = blk >> 1;                    // n*C + c  (BLOCKS_PER_PLANE = 2)
    const int half  = blk & 1;
    const int c = plane & (C - 1);
    const int lane = threadIdx.x & 31;
    const int warp = threadIdx.x >> 5;

    const float* w = weight + c * 9;
    const float w00 = __ldg(w + 0), w01 = __ldg(w + 1), w02 = __ldg(w + 2);
    const float w10 = __ldg(w + 3), w11 = __ldg(w + 4), w12 = __ldg(w + 5);
    const float w20 = __ldg(w + 6), w21 = __ldg(w + 7), w22 = __ldg(w + 8);
    const float b = __ldg(bias + c);

    const int y0 = (half * WARPS + warp) * ROWS_PER_WARP;
    const size_t base = (size_t)plane * (H * W4) + (size_t)y0 * W4 + lane;
    const float4* __restrict__ rd = reinterpret_cast<const float4*>(x) + base;
    float4* __restrict__ wr = reinterpret_cast<float4*>(out) + base;

    const float4 Z = make_float4(0.f, 0.f, 0.f, 0.f);
    const bool last_strip = (y0 + ROWS_PER_WARP >= H);

    // Window head: rows y0-1 and y0.
    float4 qm = (y0 > 0) ? __ldcs(rd - W4) : Z;
    float4 qc = __ldcs(rd);

    // Batch 0 burst: rows y0+1 .. y0+8 (4KB contiguous per warp).
    float4 p[B];
    #pragma unroll
    for (int i = 0; i < B; ++i) p[i] = __ldcs(rd + (i + 1) * W4);

    // Batch 1 burst issued BEFORE batch 0 compute: rows y0+9 .. y0+16.
    float4 n[B];
    #pragma unroll
    for (int i = 0; i < B - 1; ++i) n[i] = __ldcs(rd + (B + 1 + i) * W4);
    n[B - 1] = last_strip ? Z : __ldcs(rd + 2 * B * W4);

    float lm, rm, lc, rc;
    halos(qm, lane, lm, rm);
    halos(qc, lane, lc, rc);

    // Compute batch 0 (overlapped with batch 1's loads in flight).
    #pragma unroll
    for (int i = 0; i < B; ++i) {
        float lp, rp;
        halos(p[i], lane, lp, rp);

        float4 acc = make_float4(b, b, b, b);
        row_contrib(acc, qm, lm, rm, w00, w01, w02);
        row_contrib(acc, qc, lc, rc, w10, w11, w12);
        row_contrib(acc, p[i], lp, rp, w20, w21, w22);

        __stcs(wr + i * W4, acc);

        qm = qc; lm = lc; rm = rc;
        qc = p[i]; lc = lp; rc = rp;
    }

    // Compute batch 1.
    #pragma unroll
    for (int i = 0; i < B; ++i) {
        float lp, rp;
        halos(n[i], lane, lp, rp);

        float4 acc = make_float4(b, b, b, b);
        row_contrib(acc, qm, lm, rm, w00, w01, w02);
        row_contrib(acc, qc, lc, rc, w10, w11, w12);
        row_contrib(acc, n[i], lp, rp, w20, w21, w22);

        __stcs(wr + (B + i) * W4, acc);

        qm = qc; lm = lc; rm = rc;
        qc = n[i]; lc = lp; rc = rp;
    }
}

extern "C" void kernel_launch(void* const* d_in, const int* in_sizes, int n_in,
                              void* d_out, int out_size) {
    const float* x      = (const float*)d_in[0];
    const float* weight = (const float*)d_in[1];
    const float* bias   = (const float*)d_in[2];
    float* out          = (float*)d_out;

    const int n_blocks = 16 * C * BLOCKS_PER_PLANE;   // 8192
    dwconv3x3_kernel<<<n_blocks, THREADS>>>(x, weight, bias, out);
}